// round 2
// baseline (speedup 1.0000x reference)
#include <cuda_runtime.h>
#include <cuda_bf16.h>
#include <math.h>

// Problem constants
#define B_DIM 64
#define S_DIM 512
#define ROWS_TOTAL (B_DIM * S_DIM)   // 32768
#define K_DIM 1024
#define ANCHORS 8
#define NOUT 16                      // ANCHOR_NUM * CLASS_NUM
#define PRED_ELEMS (ROWS_TOTAL * ANCHORS)  // 262144

// Tiling
#define ROWS_PER_WARP 4
#define WARPS_PER_BLOCK 8
#define THREADS_PER_BLOCK (WARPS_PER_BLOCK * 32)
#define ROWS_PER_BLOCK (ROWS_PER_WARP * WARPS_PER_BLOCK)  // 32
#define NUM_BLOCKS (ROWS_TOTAL / ROWS_PER_BLOCK)          // 1024

// Scratch for loss reduction (no cudaMalloc allowed)
__device__ double g_nll_sum;
__device__ unsigned int g_valid_cnt;

__global__ void init_scratch_kernel() {
    g_nll_sum = 0.0;
    g_valid_cnt = 0u;
}

__global__ __launch_bounds__(THREADS_PER_BLOCK)
void rpn_main_kernel(const float4* __restrict__ X4,   // [ROWS_TOTAL][256] float4
                     const float4* __restrict__ W4,   // [1024][4] float4  (row k: 16 floats)
                     const float*  __restrict__ bias, // [16]
                     const int*    __restrict__ labels, // [ROWS_TOTAL][8]
                     float* __restrict__ out)
{
    const int warp_id = blockIdx.x * WARPS_PER_BLOCK + (threadIdx.x >> 5);
    const int lane = threadIdx.x & 31;
    const int row0 = warp_id * ROWS_PER_WARP;

    float acc[ROWS_PER_WARP][NOUT];
#pragma unroll
    for (int r = 0; r < ROWS_PER_WARP; ++r)
#pragma unroll
        for (int n = 0; n < NOUT; ++n) acc[r][n] = 0.0f;

    // K loop: each lane handles float4 index k4 = c*32 + lane  (k = 4*k4 .. 4*k4+3)
#pragma unroll 1
    for (int c = 0; c < 8; ++c) {
        const int k4 = c * 32 + lane;
        float4 xv[ROWS_PER_WARP];
#pragma unroll
        for (int r = 0; r < ROWS_PER_WARP; ++r)
            xv[r] = X4[(size_t)(row0 + r) * 256 + k4];

#pragma unroll
        for (int e = 0; e < 4; ++e) {
            const int k = k4 * 4 + e;
            const float4 w0 = __ldg(&W4[k * 4 + 0]);
            const float4 w1 = __ldg(&W4[k * 4 + 1]);
            const float4 w2 = __ldg(&W4[k * 4 + 2]);
            const float4 w3 = __ldg(&W4[k * 4 + 3]);
#pragma unroll
            for (int r = 0; r < ROWS_PER_WARP; ++r) {
                const float xs = (e == 0) ? xv[r].x :
                                 (e == 1) ? xv[r].y :
                                 (e == 2) ? xv[r].z : xv[r].w;
                acc[r][0]  = fmaf(xs, w0.x, acc[r][0]);
                acc[r][1]  = fmaf(xs, w0.y, acc[r][1]);
                acc[r][2]  = fmaf(xs, w0.z, acc[r][2]);
                acc[r][3]  = fmaf(xs, w0.w, acc[r][3]);
                acc[r][4]  = fmaf(xs, w1.x, acc[r][4]);
                acc[r][5]  = fmaf(xs, w1.y, acc[r][5]);
                acc[r][6]  = fmaf(xs, w1.z, acc[r][6]);
                acc[r][7]  = fmaf(xs, w1.w, acc[r][7]);
                acc[r][8]  = fmaf(xs, w2.x, acc[r][8]);
                acc[r][9]  = fmaf(xs, w2.y, acc[r][9]);
                acc[r][10] = fmaf(xs, w2.z, acc[r][10]);
                acc[r][11] = fmaf(xs, w2.w, acc[r][11]);
                acc[r][12] = fmaf(xs, w3.x, acc[r][12]);
                acc[r][13] = fmaf(xs, w3.y, acc[r][13]);
                acc[r][14] = fmaf(xs, w3.z, acc[r][14]);
                acc[r][15] = fmaf(xs, w3.w, acc[r][15]);
            }
        }
    }

    // Cross-lane reduction: every lane ends with the full dot products.
#pragma unroll
    for (int r = 0; r < ROWS_PER_WARP; ++r)
#pragma unroll
        for (int n = 0; n < NOUT; ++n) {
            float v = acc[r][n];
            v += __shfl_xor_sync(0xffffffffu, v, 16);
            v += __shfl_xor_sync(0xffffffffu, v, 8);
            v += __shfl_xor_sync(0xffffffffu, v, 4);
            v += __shfl_xor_sync(0xffffffffu, v, 2);
            v += __shfl_xor_sync(0xffffffffu, v, 1);
            acc[r][n] = v;
        }

    // Epilogue: lane = r*8 + a covers the 4 rows x 8 anchors of this warp tile.
    const int r = lane >> 3;
    const int a = lane & 7;
    const int row = row0 + r;

    float l0 = 0.f, l1 = 0.f;
#pragma unroll
    for (int rr = 0; rr < ROWS_PER_WARP; ++rr) {
#pragma unroll
        for (int n = 0; n < NOUT; ++n) {
            if (rr == r && n == 2 * a)     l0 = acc[rr][n];
            if (rr == r && n == 2 * a + 1) l1 = acc[rr][n];
        }
    }
    l0 += bias[2 * a];
    l1 += bias[2 * a + 1];

    const int lab = labels[row * ANCHORS + a];
    const bool valid = (lab != -1);
    const int pred = (l1 > l0) ? 1 : 0;  // argmax, first-max on tie -> 0

    // stable 2-class log-sum-exp
    const float m  = fmaxf(l0, l1);
    const float mn = fminf(l0, l1);
    const float lse = m + log1pf(expf(mn - m));
    const float picked = (lab > 0) ? l1 : l0;  // lab in {-1,0,1}; clamp(-1)->0 picks l0
    const float nll = valid ? (lse - picked) : 0.0f;

    // outputs: [0]=loss, [1 .. 1+PRED) = predict_label, [1+PRED .. ) = candidate_mask
    const int idx = row * ANCHORS + a;
    out[1 + idx] = (float)pred;
    out[1 + PRED_ELEMS + idx] = (pred == 1 && valid) ? 1.0f : 0.0f;

    // warp-reduce nll and valid count, one atomic pair per warp
    float nll_w = nll;
    int cnt_w = valid ? 1 : 0;
    nll_w += __shfl_xor_sync(0xffffffffu, nll_w, 16);
    nll_w += __shfl_xor_sync(0xffffffffu, nll_w, 8);
    nll_w += __shfl_xor_sync(0xffffffffu, nll_w, 4);
    nll_w += __shfl_xor_sync(0xffffffffu, nll_w, 2);
    nll_w += __shfl_xor_sync(0xffffffffu, nll_w, 1);
    cnt_w += __shfl_xor_sync(0xffffffffu, cnt_w, 16);
    cnt_w += __shfl_xor_sync(0xffffffffu, cnt_w, 8);
    cnt_w += __shfl_xor_sync(0xffffffffu, cnt_w, 4);
    cnt_w += __shfl_xor_sync(0xffffffffu, cnt_w, 2);
    cnt_w += __shfl_xor_sync(0xffffffffu, cnt_w, 1);
    if (lane == 0) {
        atomicAdd(&g_nll_sum, (double)nll_w);
        atomicAdd(&g_valid_cnt, (unsigned int)cnt_w);
    }
}

__global__ void finalize_kernel(float* __restrict__ out) {
    const double cnt = (double)g_valid_cnt;
    const double denom = cnt > 1.0 ? cnt : 1.0;
    out[0] = (float)(g_nll_sum / denom);
}

extern "C" void kernel_launch(void* const* d_in, const int* in_sizes, int n_in,
                              void* d_out, int out_size) {
    const float4* X4 = (const float4*)d_in[0];      // batch_input (64,512,1024) f32
    const float4* W4 = (const float4*)d_in[1];      // W (1024,16) f32
    const float*  b  = (const float*)d_in[2];       // b (16,) f32
    const int*    lb = (const int*)d_in[3];         // anchor_labels (64,512,8) i32
    float* out = (float*)d_out;

    init_scratch_kernel<<<1, 1>>>();
    rpn_main_kernel<<<NUM_BLOCKS, THREADS_PER_BLOCK>>>(X4, W4, b, lb, out);
    finalize_kernel<<<1, 1>>>(out);
}

// round 3
// speedup vs baseline: 1.9553x; 1.9553x over previous
#include <cuda_runtime.h>
#include <cuda_bf16.h>
#include <math.h>

// Problem constants
#define B_DIM 64
#define S_DIM 512
#define ROWS_TOTAL (B_DIM * S_DIM)          // 32768
#define K_DIM 1024
#define ANCHORS 8
#define NOUT 16                             // ANCHOR_NUM * CLASS_NUM
#define PRED_ELEMS (ROWS_TOTAL * ANCHORS)   // 262144

// Tiling
#define ROWS_PER_WARP 4
#define WARPS_PER_BLOCK 8
#define THREADS_PER_BLOCK (WARPS_PER_BLOCK * 32)
#define ROWS_PER_BLOCK (ROWS_PER_WARP * WARPS_PER_BLOCK)  // 32
#define NUM_BLOCKS (ROWS_TOTAL / ROWS_PER_BLOCK)          // 1024

// W in shared: padded row stride of 18 floats (72B, 8B-aligned).
// LDS.64 phase = 16 lanes; banks 18*L mod 32 are distinct for L=0..15 -> conflict-free.
#define W_STRIDE 18
#define W_SMEM_BYTES (K_DIM * W_STRIDE * 4)   // 73728

// Per-block partial sums (no cudaMalloc allowed; every slot written each run -> no init kernel)
__device__ float g_part_nll[NUM_BLOCKS];
__device__ int   g_part_cnt[NUM_BLOCKS];

__device__ __forceinline__ void fma2(unsigned long long& d,
                                     unsigned long long a,
                                     unsigned long long b) {
    asm("fma.rn.f32x2 %0, %1, %2, %0;" : "+l"(d) : "l"(a), "l"(b));
}

__device__ __forceinline__ unsigned long long pack_dup(float x) {
    unsigned long long r;
    asm("mov.b64 %0, {%1, %1};" : "=l"(r) : "r"(__float_as_uint(x)));
    return r;
}

__device__ __forceinline__ void unpack2(unsigned long long v, float& lo, float& hi) {
    unsigned int l, h;
    asm("mov.b64 {%0, %1}, %2;" : "=r"(l), "=r"(h) : "l"(v));
    lo = __uint_as_float(l);
    hi = __uint_as_float(h);
}

__global__ __launch_bounds__(THREADS_PER_BLOCK, 2)
void rpn_main_kernel(const float4* __restrict__ X4,    // [ROWS_TOTAL][256] float4
                     const float*  __restrict__ Wg,    // [1024][16]
                     const float*  __restrict__ bias,  // [16]
                     const int*    __restrict__ labels,// [ROWS_TOTAL][8]
                     float* __restrict__ out)
{
    extern __shared__ float Wsh[];   // [1024][18] padded
    __shared__ float s_nll[WARPS_PER_BLOCK];
    __shared__ int   s_cnt[WARPS_PER_BLOCK];

    const int tid  = threadIdx.x;
    const int wid  = tid >> 5;
    const int lane = tid & 31;
    const int warp_id = blockIdx.x * WARPS_PER_BLOCK + wid;
    const int row0 = warp_id * ROWS_PER_WARP;

    // Stage W into padded shared (coalesced global reads)
    for (int i = tid; i < K_DIM * NOUT; i += THREADS_PER_BLOCK) {
        const int k = i >> 4;
        const int n = i & 15;
        Wsh[k * W_STRIDE + n] = Wg[i];
    }
    __syncthreads();

    // acc[r][p] packs outputs (2p, 2p+1) = (anchor p class0, class1) for row r
    unsigned long long acc[ROWS_PER_WARP][ANCHORS];
#pragma unroll
    for (int r = 0; r < ROWS_PER_WARP; ++r)
#pragma unroll
        for (int p = 0; p < ANCHORS; ++p) acc[r][p] = 0ULL;

#pragma unroll 1
    for (int c = 0; c < 8; ++c) {
        const int k4 = c * 32 + lane;     // float4 index into X row
        float4 xv[ROWS_PER_WARP];
#pragma unroll
        for (int r = 0; r < ROWS_PER_WARP; ++r)
            xv[r] = X4[(size_t)(row0 + r) * 256 + k4];

#pragma unroll
        for (int e = 0; e < 4; ++e) {
            const int k = k4 * 4 + e;
            const unsigned long long* wrow =
                reinterpret_cast<const unsigned long long*>(&Wsh[k * W_STRIDE]);
            unsigned long long wp[ANCHORS];
#pragma unroll
            for (int p = 0; p < ANCHORS; ++p) wp[p] = wrow[p];

#pragma unroll
            for (int r = 0; r < ROWS_PER_WARP; ++r) {
                const float xs = (e == 0) ? xv[r].x :
                                 (e == 1) ? xv[r].y :
                                 (e == 2) ? xv[r].z : xv[r].w;
                const unsigned long long xx = pack_dup(xs);
#pragma unroll
                for (int p = 0; p < ANCHORS; ++p)
                    fma2(acc[r][p], xx, wp[p]);
            }
        }
    }

    // Unpack packed accumulators to scalar logits
    float accf[ROWS_PER_WARP][NOUT];
#pragma unroll
    for (int r = 0; r < ROWS_PER_WARP; ++r)
#pragma unroll
        for (int p = 0; p < ANCHORS; ++p)
            unpack2(acc[r][p], accf[r][2 * p], accf[r][2 * p + 1]);

    // Cross-lane reduction: every lane ends with the full dot products.
#pragma unroll
    for (int r = 0; r < ROWS_PER_WARP; ++r)
#pragma unroll
        for (int n = 0; n < NOUT; ++n) {
            float v = accf[r][n];
            v += __shfl_xor_sync(0xffffffffu, v, 16);
            v += __shfl_xor_sync(0xffffffffu, v, 8);
            v += __shfl_xor_sync(0xffffffffu, v, 4);
            v += __shfl_xor_sync(0xffffffffu, v, 2);
            v += __shfl_xor_sync(0xffffffffu, v, 1);
            accf[r][n] = v;
        }

    // Epilogue: lane = r*8 + a covers 4 rows x 8 anchors of this warp tile.
    const int r = lane >> 3;
    const int a = lane & 7;
    const int row = row0 + r;

    float l0 = 0.f, l1 = 0.f;
#pragma unroll
    for (int rr = 0; rr < ROWS_PER_WARP; ++rr)
#pragma unroll
        for (int n = 0; n < NOUT; ++n) {
            if (rr == r && n == 2 * a)     l0 = accf[rr][n];
            if (rr == r && n == 2 * a + 1) l1 = accf[rr][n];
        }
    l0 += bias[2 * a];
    l1 += bias[2 * a + 1];

    const int lab = labels[row * ANCHORS + a];
    const bool valid = (lab != -1);
    const int pred = (l1 > l0) ? 1 : 0;  // argmax, tie -> 0

    // stable 2-class log-sum-exp
    const float m  = fmaxf(l0, l1);
    const float mn = fminf(l0, l1);
    const float lse = m + log1pf(expf(mn - m));
    const float picked = (lab > 0) ? l1 : l0;   // clamp(-1)->0 picks l0
    const float nll = valid ? (lse - picked) : 0.0f;

    // outputs: [0]=loss, [1 .. 1+PRED) = predict_label, then candidate_mask
    const int idx = row * ANCHORS + a;          // = row0*8 + lane  (coalesced)
    out[1 + idx] = (float)pred;
    out[1 + PRED_ELEMS + idx] = (pred == 1 && valid) ? 1.0f : 0.0f;

    // warp reduce nll / count
    float nll_w = nll;
    int cnt_w = valid ? 1 : 0;
#pragma unroll
    for (int s = 16; s > 0; s >>= 1) {
        nll_w += __shfl_xor_sync(0xffffffffu, nll_w, s);
        cnt_w += __shfl_xor_sync(0xffffffffu, cnt_w, s);
    }
    if (lane == 0) { s_nll[wid] = nll_w; s_cnt[wid] = cnt_w; }
    __syncthreads();

    if (wid == 0) {
        float bn = (lane < WARPS_PER_BLOCK) ? s_nll[lane] : 0.0f;
        int   bc = (lane < WARPS_PER_BLOCK) ? s_cnt[lane] : 0;
#pragma unroll
        for (int s = 4; s > 0; s >>= 1) {
            bn += __shfl_xor_sync(0xffffffffu, bn, s);
            bc += __shfl_xor_sync(0xffffffffu, bc, s);
        }
        if (lane == 0) {
            g_part_nll[blockIdx.x] = bn;
            g_part_cnt[blockIdx.x] = bc;
        }
    }
}

__global__ __launch_bounds__(256)
void finalize_kernel(float* __restrict__ out) {
    __shared__ double s_sum[8];
    __shared__ int    s_c[8];
    const int tid = threadIdx.x;
    const int lane = tid & 31;
    const int wid = tid >> 5;

    double sum = 0.0;
    int cnt = 0;
#pragma unroll
    for (int i = 0; i < NUM_BLOCKS / 256; ++i) {
        const int b = tid + i * 256;
        sum += (double)g_part_nll[b];
        cnt += g_part_cnt[b];
    }
#pragma unroll
    for (int s = 16; s > 0; s >>= 1) {
        sum += __shfl_xor_sync(0xffffffffu, sum, s);
        cnt += __shfl_xor_sync(0xffffffffu, cnt, s);
    }
    if (lane == 0) { s_sum[wid] = sum; s_c[wid] = cnt; }
    __syncthreads();
    if (tid == 0) {
        double t = 0.0; int c = 0;
        for (int i = 0; i < 8; ++i) { t += s_sum[i]; c += s_c[i]; }
        const double denom = c > 1 ? (double)c : 1.0;
        out[0] = (float)(t / denom);
    }
}

extern "C" void kernel_launch(void* const* d_in, const int* in_sizes, int n_in,
                              void* d_out, int out_size) {
    const float4* X4 = (const float4*)d_in[0];   // batch_input (64,512,1024) f32
    const float*  Wg = (const float*)d_in[1];    // W (1024,16) f32
    const float*  b  = (const float*)d_in[2];    // b (16,) f32
    const int*    lb = (const int*)d_in[3];      // anchor_labels (64,512,8) i32
    float* out = (float*)d_out;

    cudaFuncSetAttribute(rpn_main_kernel,
                         cudaFuncAttributeMaxDynamicSharedMemorySize, W_SMEM_BYTES);
    rpn_main_kernel<<<NUM_BLOCKS, THREADS_PER_BLOCK, W_SMEM_BYTES>>>(X4, Wg, b, lb, out);
    finalize_kernel<<<1, 256>>>(out);
}